// round 2
// baseline (speedup 1.0000x reference)
#include <cuda_runtime.h>

// Problem constants
#define D_MODEL 512
#define NHEADS  8
#define DK      64
#define BATCH   2
#define SEQ     4096
#define MROWS   (BATCH * SEQ)                  // 8192
#define OUT_ELEMS  (BATCH * SEQ * D_MODEL)     // 4194304
#define ATTN_ELEMS (268435456LL)               // B*H*S*S
#define NTILES  (SEQ / 64)                     // 64
#define NPAIRS  (NTILES * (NTILES + 1) / 2)    // 2080 lower-tri tile pairs

// Scratch (static device globals — no runtime allocation)
__device__ float g_q[MROWS * D_MODEL];
__device__ float g_k[MROWS * D_MODEL];
__device__ float g_v[MROWS * D_MODEL];
__device__ float g_o[MROWS * D_MODEL];
__device__ float g_attn_scratch[268435456];    // 1 GiB, used only if attn not in d_out

// ---------------------------------------------------------------------------
// Packed f32x2 helpers (Blackwell FFMA2 — 2x fp32 throughput, IEEE-exact)
// ---------------------------------------------------------------------------
typedef unsigned long long u64t;

__device__ __forceinline__ u64t pack2(float lo, float hi) {
    u64t r;
    asm("mov.b64 %0, {%1, %2};" : "=l"(r) : "f"(lo), "f"(hi));
    return r;
}
__device__ __forceinline__ u64t splat2(float x) {
    u64t r;
    asm("mov.b64 %0, {%1, %1};" : "=l"(r) : "f"(x));
    return r;
}
__device__ __forceinline__ void ffma2(u64t& d, u64t a, u64t b) {
    asm("fma.rn.f32x2 %0, %1, %2, %0;" : "+l"(d) : "l"(a), "l"(b));
}
__device__ __forceinline__ void unpack2(u64t v, float& lo, float& hi) {
    asm("mov.b64 {%0, %1}, %2;" : "=f"(lo), "=f"(hi) : "l"(v));
}

// ---------------------------------------------------------------------------
// Generic 64x64-tile GEMM body: C[M,N] = A[M,K] @ W[N,K]^T + bias
// M=8192, N=512, K=512 for all four dense GEMMs. Block (16,16), each thread 4x4.
// Accumulation in packed f32x2 pairs (j-pairs), bit-identical to scalar fp32.
// ---------------------------------------------------------------------------
__device__ __forceinline__ void gemm512_body(const float* __restrict__ A,
                                             const float* __restrict__ W,
                                             const float* __restrict__ bias,
                                             float* __restrict__ C)
{
    const int K = D_MODEL, N = D_MODEL;
    __shared__ float As[64][33];
    __shared__ float Ws[64][33];
    const int tx = threadIdx.x, ty = threadIdx.y;
    const int tid = ty * 16 + tx;
    const int rowBase = blockIdx.y * 64;
    const int colBase = blockIdx.x * 64;

    u64t acc[4][2];
    #pragma unroll
    for (int i = 0; i < 4; i++) { acc[i][0] = 0ull; acc[i][1] = 0ull; }

    for (int k0 = 0; k0 < K; k0 += 32) {
        #pragma unroll
        for (int r = 0; r < 8; r++) {
            int lin = tid + r * 256;
            int rr = lin >> 5, cc = lin & 31;
            As[rr][cc] = A[(size_t)(rowBase + rr) * K + k0 + cc];
            Ws[rr][cc] = W[(size_t)(colBase + rr) * K + k0 + cc];
        }
        __syncthreads();
        #pragma unroll
        for (int kk = 0; kk < 32; kk++) {
            float a0 = As[ty * 4 + 0][kk], a1 = As[ty * 4 + 1][kk];
            float a2 = As[ty * 4 + 2][kk], a3 = As[ty * 4 + 3][kk];
            float b0 = Ws[tx * 4 + 0][kk], b1 = Ws[tx * 4 + 1][kk];
            float b2 = Ws[tx * 4 + 2][kk], b3 = Ws[tx * 4 + 3][kk];
            u64t bp0 = pack2(b0, b1), bp1 = pack2(b2, b3);
            u64t s0 = splat2(a0), s1 = splat2(a1), s2 = splat2(a2), s3 = splat2(a3);
            ffma2(acc[0][0], s0, bp0); ffma2(acc[0][1], s0, bp1);
            ffma2(acc[1][0], s1, bp0); ffma2(acc[1][1], s1, bp1);
            ffma2(acc[2][0], s2, bp0); ffma2(acc[2][1], s2, bp1);
            ffma2(acc[3][0], s3, bp0); ffma2(acc[3][1], s3, bp1);
        }
        __syncthreads();
    }
    #pragma unroll
    for (int i = 0; i < 4; i++) {
        float c0, c1, c2, c3;
        unpack2(acc[i][0], c0, c1);
        unpack2(acc[i][1], c2, c3);
        float cv[4] = {c0, c1, c2, c3};
        #pragma unroll
        for (int j = 0; j < 4; j++) {
            int gc = colBase + tx * 4 + j;
            C[(size_t)(rowBase + ty * 4 + i) * N + gc] = cv[j] + bias[gc];
        }
    }
}

// Projection GEMMs: write into g_q / g_k / g_v selected by `which`
__global__ void mha_proj_kernel(const float* __restrict__ X,
                                const float* __restrict__ W,
                                const float* __restrict__ bias,
                                int which)
{
    float* dst = (which == 0) ? g_q : (which == 1) ? g_k : g_v;
    gemm512_body(X, W, bias, dst);
}

// Final projection: out = g_o @ Wo^T + bo
__global__ void mha_final_kernel(const float* __restrict__ W,
                                 const float* __restrict__ bias,
                                 float* __restrict__ C)
{
    gemm512_body(g_o, W, bias, C);
}

// ---------------------------------------------------------------------------
// Scores: attn[bh, i, j] = (q_bh[i,:] . k_bh[j,:]) / 8 for lower-tri 64x64 tiles
// grid: (NPAIRS, B*H), block (16,16)
// ---------------------------------------------------------------------------
__global__ void mha_scores_kernel(float* attn_io)
{
    float* attn = attn_io ? attn_io : g_attn_scratch;
    int t  = blockIdx.x;
    int bh = blockIdx.y;
    // map linear index -> (ti, tj), tj <= ti
    int ti = (int)((sqrtf(8.0f * (float)t + 1.0f) - 1.0f) * 0.5f);
    while ((ti + 1) * (ti + 2) / 2 <= t) ti++;
    while (ti * (ti + 1) / 2 > t) ti--;
    int tj = t - ti * (ti + 1) / 2;

    int b = bh >> 3, h = bh & 7;
    const float* qb = g_q + (size_t)b * SEQ * D_MODEL + h * DK;
    const float* kb = g_k + (size_t)b * SEQ * D_MODEL + h * DK;

    __shared__ float Qs[64][65];
    __shared__ float Ks[64][65];
    const int tx = threadIdx.x, ty = threadIdx.y;
    const int tid = ty * 16 + tx;

    #pragma unroll
    for (int r = 0; r < 16; r++) {
        int lin = tid + r * 256;
        int rr = lin >> 6, cc = lin & 63;
        Qs[rr][cc] = qb[(size_t)(ti * 64 + rr) * D_MODEL + cc];
        Ks[rr][cc] = kb[(size_t)(tj * 64 + rr) * D_MODEL + cc];
    }
    __syncthreads();

    u64t acc[4][2];
    #pragma unroll
    for (int i = 0; i < 4; i++) { acc[i][0] = 0ull; acc[i][1] = 0ull; }

    #pragma unroll
    for (int kk = 0; kk < 64; kk++) {
        float a0 = Qs[ty * 4 + 0][kk], a1 = Qs[ty * 4 + 1][kk];
        float a2 = Qs[ty * 4 + 2][kk], a3 = Qs[ty * 4 + 3][kk];
        float b0 = Ks[tx * 4 + 0][kk], b1 = Ks[tx * 4 + 1][kk];
        float b2 = Ks[tx * 4 + 2][kk], b3 = Ks[tx * 4 + 3][kk];
        u64t bp0 = pack2(b0, b1), bp1 = pack2(b2, b3);
        u64t s0 = splat2(a0), s1 = splat2(a1), s2 = splat2(a2), s3 = splat2(a3);
        ffma2(acc[0][0], s0, bp0); ffma2(acc[0][1], s0, bp1);
        ffma2(acc[1][0], s1, bp0); ffma2(acc[1][1], s1, bp1);
        ffma2(acc[2][0], s2, bp0); ffma2(acc[2][1], s2, bp1);
        ffma2(acc[3][0], s3, bp0); ffma2(acc[3][1], s3, bp1);
    }

    const float scale = 0.125f;  // 1/sqrt(64)
    float* ob = attn + ((size_t)bh * SEQ + ti * 64) * SEQ + tj * 64;
    #pragma unroll
    for (int i = 0; i < 4; i++) {
        float c0, c1, c2, c3;
        unpack2(acc[i][0], c0, c1);
        unpack2(acc[i][1], c2, c3);
        float cv[4] = {c0, c1, c2, c3};
        #pragma unroll
        for (int j = 0; j < 4; j++)
            ob[(size_t)(ty * 4 + i) * SEQ + tx * 4 + j] = cv[j] * scale;
    }
    // tiles with tj > ti are never written; softmax writes exact zeros there.
}

// ---------------------------------------------------------------------------
// Row softmax (causal): one block (256 thr) per row. Registers hold the row.
// Writes exact 0.0 for j > i (matches reference's exp(-1e9 - max) == 0 in fp32).
// ---------------------------------------------------------------------------
__device__ __forceinline__ float warp_max(float v) {
    #pragma unroll
    for (int o = 16; o; o >>= 1) v = fmaxf(v, __shfl_xor_sync(0xffffffffu, v, o));
    return v;
}
__device__ __forceinline__ float warp_sum(float v) {
    #pragma unroll
    for (int o = 16; o; o >>= 1) v += __shfl_xor_sync(0xffffffffu, v, o);
    return v;
}

__global__ void mha_softmax_kernel(float* attn_io)
{
    float* attn = attn_io ? attn_io : g_attn_scratch;
    const int row = blockIdx.x;            // bh*S + i
    const int i = row & (SEQ - 1);
    const int L = i + 1;
    float* p = attn + (size_t)row * SEQ;
    const int tid = threadIdx.x;

    float vals[16];
    float mx = -1e30f;
    #pragma unroll
    for (int v = 0; v < 16; v++) {
        int j = tid + v * 256;
        float x = (j < L) ? p[j] : -1e30f;
        vals[v] = x;
        mx = fmaxf(mx, x);
    }

    __shared__ float red[8];
    mx = warp_max(mx);
    if ((tid & 31) == 0) red[tid >> 5] = mx;
    __syncthreads();
    float m = red[0];
    #pragma unroll
    for (int w = 1; w < 8; w++) m = fmaxf(m, red[w]);
    __syncthreads();

    float sum = 0.0f;
    #pragma unroll
    for (int v = 0; v < 16; v++) {
        int j = tid + v * 256;
        if (j < L) { float e = __expf(vals[v] - m); vals[v] = e; sum += e; }
        else       { vals[v] = 0.0f; }
    }
    sum = warp_sum(sum);
    if ((tid & 31) == 0) red[tid >> 5] = sum;
    __syncthreads();
    float total = 0.0f;
    #pragma unroll
    for (int w = 0; w < 8; w++) total += red[w];
    float inv = 1.0f / total;

    #pragma unroll
    for (int v = 0; v < 16; v++)
        p[tid + v * 256] = vals[v] * inv;   // zeros beyond L
}

// ---------------------------------------------------------------------------
// AV: o[b, i, h*64:+64] = sum_{j<=i} attn[bh,i,j] * v[b,j,h*64:+64]
// grid: (NTILES, B*H). Skips k-tiles above the diagonal (attn==0 beyond i).
// ---------------------------------------------------------------------------
__global__ void mha_av_kernel(const float* attn_io)
{
    const float* attn = attn_io ? attn_io : g_attn_scratch;
    int ti = blockIdx.x;
    int bh = blockIdx.y;
    int b = bh >> 3, h = bh & 7;

    __shared__ float As[64][65];
    __shared__ float Vs[64][65];
    const int tx = threadIdx.x, ty = threadIdx.y;
    const int tid = ty * 16 + tx;

    u64t acc[4][2];
    #pragma unroll
    for (int i = 0; i < 4; i++) { acc[i][0] = 0ull; acc[i][1] = 0ull; }

    for (int jt = 0; jt <= ti; jt++) {
        #pragma unroll
        for (int r = 0; r < 16; r++) {
            int lin = tid + r * 256;
            int rr = lin >> 6, cc = lin & 63;
            As[rr][cc] = attn[((size_t)bh * SEQ + ti * 64 + rr) * SEQ + jt * 64 + cc];
            Vs[rr][cc] = g_v[(size_t)(b * SEQ + jt * 64 + rr) * D_MODEL + h * DK + cc];
        }
        __syncthreads();
        #pragma unroll
        for (int kk = 0; kk < 64; kk++) {
            float a0 = As[ty * 4 + 0][kk], a1 = As[ty * 4 + 1][kk];
            float a2 = As[ty * 4 + 2][kk], a3 = As[ty * 4 + 3][kk];
            float b0 = Vs[kk][tx * 4 + 0], b1 = Vs[kk][tx * 4 + 1];
            float b2 = Vs[kk][tx * 4 + 2], b3 = Vs[kk][tx * 4 + 3];
            u64t bp0 = pack2(b0, b1), bp1 = pack2(b2, b3);
            u64t s0 = splat2(a0), s1 = splat2(a1), s2 = splat2(a2), s3 = splat2(a3);
            ffma2(acc[0][0], s0, bp0); ffma2(acc[0][1], s0, bp1);
            ffma2(acc[1][0], s1, bp0); ffma2(acc[1][1], s1, bp1);
            ffma2(acc[2][0], s2, bp0); ffma2(acc[2][1], s2, bp1);
            ffma2(acc[3][0], s3, bp0); ffma2(acc[3][1], s3, bp1);
        }
        __syncthreads();
    }

    #pragma unroll
    for (int i = 0; i < 4; i++) {
        float c0, c1, c2, c3;
        unpack2(acc[i][0], c0, c1);
        unpack2(acc[i][1], c2, c3);
        float cv[4] = {c0, c1, c2, c3};
        #pragma unroll
        for (int j = 0; j < 4; j++)
            g_o[(size_t)(b * SEQ + ti * 64 + ty * 4 + i) * D_MODEL + h * DK + tx * 4 + j]
                = cv[j];
    }
}

// ---------------------------------------------------------------------------
extern "C" void kernel_launch(void* const* d_in, const int* in_sizes, int n_in,
                              void* d_out, int out_size)
{
    const float* Q  = (const float*)d_in[0];
    const float* K  = (const float*)d_in[1];
    const float* V  = (const float*)d_in[2];
    const float* Wq = (const float*)d_in[3];
    const float* bq = (const float*)d_in[4];
    const float* Wk = (const float*)d_in[5];
    const float* bk = (const float*)d_in[6];
    const float* Wv = (const float*)d_in[7];
    const float* bv = (const float*)d_in[8];
    const float* Wo = (const float*)d_in[9];
    const float* bo = (const float*)d_in[10];

    float* outp = (float*)d_out;
    long long oe = (long long)out_size;

    float* final_out = nullptr;   // where `out` [B,S,D] goes (nullptr = skip)
    float* attn_io   = nullptr;   // where `attn` [B,H,S,S] goes (nullptr = scratch)
    if (oe >= (long long)OUT_ELEMS + ATTN_ELEMS) {
        final_out = outp;
        attn_io   = outp + OUT_ELEMS;
    } else if (oe >= ATTN_ELEMS) {
        attn_io = outp;           // attn-only output
    } else {
        final_out = outp;         // out-only output; attn in device scratch
    }

    dim3 blk(16, 16);
    dim3 gproj(D_MODEL / 64, MROWS / 64);          // (8, 128)

    mha_proj_kernel<<<gproj, blk>>>(Q, Wq, bq, 0);
    mha_proj_kernel<<<gproj, blk>>>(K, Wk, bk, 1);
    mha_proj_kernel<<<gproj, blk>>>(V, Wv, bv, 2);

    mha_scores_kernel<<<dim3(NPAIRS, BATCH * NHEADS), blk>>>(attn_io);
    mha_softmax_kernel<<<BATCH * NHEADS * SEQ, 256>>>(attn_io);
    mha_av_kernel<<<dim3(NTILES, BATCH * NHEADS), blk>>>(attn_io);

    if (final_out)
        mha_final_kernel<<<gproj, blk>>>(Wo, bo, final_out);
}

// round 14
// speedup vs baseline: 1.1846x; 1.1846x over previous
#include <cuda_runtime.h>

// Problem constants
#define D_MODEL 512
#define NHEADS  8
#define DK      64
#define BATCH   2
#define SEQ     4096
#define MROWS   (BATCH * SEQ)                  // 8192
#define OUT_ELEMS  (BATCH * SEQ * D_MODEL)     // 4194304
#define ATTN_ELEMS (268435456LL)               // B*H*S*S
#define NTILES  (SEQ / 64)                     // 64
#define NPAIRS  (NTILES * (NTILES + 1) / 2)    // 2080
#define TILE_WORDS (64 * 64)

// Scratch (static device globals — no runtime allocation)
__device__ float g_q[MROWS * D_MODEL];
__device__ float g_k[MROWS * D_MODEL];
__device__ float g_vt[BATCH * NHEADS * DK * SEQ];   // [b*512 + n][s]  (transposed V proj)
__device__ float g_o[MROWS * D_MODEL];
__device__ float g_attn_scratch[268435456];

typedef unsigned long long u64t;

__device__ __forceinline__ void ffma2(u64t& d, u64t a, u64t b) {
    asm("fma.rn.f32x2 %0, %1, %2, %0;" : "+l"(d) : "l"(a), "l"(b));
}
__device__ __forceinline__ float2 unpack2(u64t v) {
    float2 f; asm("mov.b64 {%0, %1}, %2;" : "=f"(f.x), "=f"(f.y) : "l"(v));
    return f;
}
__device__ __forceinline__ float accsum(u64t v) {
    float2 f = unpack2(v); return f.x + f.y;
}

// Swizzled word index within a 64x64 fp32 tile: conflict-free strided-row LDS.128
__device__ __forceinline__ int swz(int r, int k) { return r * 64 + (k ^ (r & 60)); }

// cp.async 16B helper
__device__ __forceinline__ void cp16(float* smem_dst, const float* gsrc) {
    unsigned saddr = (unsigned)__cvta_generic_to_shared(smem_dst);
    asm volatile("cp.async.cg.shared.global [%0], [%1], 16;" :: "r"(saddr), "l"(gsrc));
}
__device__ __forceinline__ void cp_commit() { asm volatile("cp.async.commit_group;"); }
__device__ __forceinline__ void cp_wait0()  { asm volatile("cp.async.wait_group 0;" ::: "memory"); }

// Async-load a 64x64 tile from row-major gmem into swizzled smem (128 threads).
__device__ __forceinline__ void cp_tile(float* __restrict__ sm,
                                        const float* __restrict__ g,
                                        int stride, int tid)
{
    #pragma unroll
    for (int it = 0; it < 8; it++) {
        int f4 = tid + it * 128;
        int r = f4 >> 4, kc = (f4 & 15) << 2;
        cp16(sm + swz(r, kc), g + (size_t)r * (size_t)stride + kc);
    }
}

// Synchronous tile load (scores kernel — kept identical to the verified R3 path)
__device__ __forceinline__ void load_tile(float* __restrict__ sm,
                                          const float* __restrict__ g,
                                          int stride, int tid)
{
    #pragma unroll
    for (int it = 0; it < 8; it++) {
        int f4 = tid + it * 128;
        int r = f4 >> 4, kc = (f4 & 15) << 2;
        float4 v = *reinterpret_cast<const float4*>(g + (size_t)r * (size_t)stride + kc);
        *reinterpret_cast<float4*>(sm + swz(r, kc)) = v;
    }
}

// Core: acc[8][4] (pairs over k) += As-rows (ty*8..+7) x Bs-rows (tx*4..+3), K=64.
// Per 4-k step: 12 LDS.128 + 64 FFMA2, no movs.
__device__ __forceinline__ void mma_tile(const float* __restrict__ As,
                                         const float* __restrict__ Bs,
                                         u64t acc[8][4], int tx, int ty)
{
    #pragma unroll
    for (int k = 0; k < 64; k += 4) {
        ulonglong2 bv[4];
        #pragma unroll
        for (int j = 0; j < 4; j++)
            bv[j] = *reinterpret_cast<const ulonglong2*>(Bs + swz(tx * 4 + j, k));
        #pragma unroll
        for (int i = 0; i < 8; i++) {
            ulonglong2 av = *reinterpret_cast<const ulonglong2*>(As + swz(ty * 8 + i, k));
            #pragma unroll
            for (int j = 0; j < 4; j++) {
                ffma2(acc[i][j], av.x, bv[j].x);
                ffma2(acc[i][j], av.y, bv[j].y);
            }
        }
    }
}

// ---------------------------------------------------------------------------
// QKV projections fused: grid (8, 128, 3); z selects {Q->g_q, K->g_k, V->g_vt}
// Double-buffered cp.async pipeline over the 8 k-chunks.
// ---------------------------------------------------------------------------
__global__ void __launch_bounds__(128) mha_qkv_kernel(
    const float* __restrict__ Qin, const float* __restrict__ Kin,
    const float* __restrict__ Vin,
    const float* __restrict__ Wq, const float* __restrict__ bq,
    const float* __restrict__ Wk, const float* __restrict__ bk,
    const float* __restrict__ Wv, const float* __restrict__ bv)
{
    extern __shared__ float smem[];            // 4 tiles: A0 B0 A1 B1
    float* As[2] = { smem,                  smem + 2 * TILE_WORDS };
    float* Bs[2] = { smem + TILE_WORDS,     smem + 3 * TILE_WORDS };

    const int tid = threadIdx.x, tx = tid & 15, ty = tid >> 4;
    const int rowBase = blockIdx.y * 64, colBase = blockIdx.x * 64;
    const int z = blockIdx.z;

    const float* X = (z == 0) ? Qin : (z == 1) ? Kin : Vin;
    const float* W = (z == 0) ? Wq : (z == 1) ? Wk : Wv;
    const float* bias = (z == 0) ? bq : (z == 1) ? bk : bv;

    u64t acc[8][4];
    #pragma unroll
    for (int i = 0; i < 8; i++)
        #pragma unroll
        for (int j = 0; j < 4; j++) acc[i][j] = 0ull;

    cp_tile(As[0], X + (size_t)rowBase * D_MODEL, D_MODEL, tid);
    cp_tile(Bs[0], W + (size_t)colBase * D_MODEL, D_MODEL, tid);
    cp_commit();
    cp_wait0();
    __syncthreads();

    for (int c = 0; c < 8; c++) {
        int cur = c & 1;
        if (c + 1 < 8) {
            cp_tile(As[1 - cur], X + (size_t)rowBase * D_MODEL + (c + 1) * 64, D_MODEL, tid);
            cp_tile(Bs[1 - cur], W + (size_t)colBase * D_MODEL + (c + 1) * 64, D_MODEL, tid);
            cp_commit();
        }
        mma_tile(As[cur], Bs[cur], acc, tx, ty);
        if (c + 1 < 8) cp_wait0();
        __syncthreads();
    }

    if (z < 2) {
        float* C = (z == 0) ? g_q : g_k;
        #pragma unroll
        for (int i = 0; i < 8; i++) {
            int m = rowBase + ty * 8 + i;
            int n0 = colBase + tx * 4;
            float4 o;
            o.x = accsum(acc[i][0]) + bias[n0 + 0];
            o.y = accsum(acc[i][1]) + bias[n0 + 1];
            o.z = accsum(acc[i][2]) + bias[n0 + 2];
            o.w = accsum(acc[i][3]) + bias[n0 + 3];
            *reinterpret_cast<float4*>(C + (size_t)m * D_MODEL + n0) = o;
        }
    } else {
        // V: write transposed into g_vt[(b*512 + n)][s]
        #pragma unroll
        for (int i = 0; i < 8; i++) {
            int m = rowBase + ty * 8 + i;
            int b = m >> 12, s = m & (SEQ - 1);
            #pragma unroll
            for (int j = 0; j < 4; j++) {
                int n = colBase + tx * 4 + j;
                g_vt[(size_t)(b * 512 + n) * SEQ + s] = accsum(acc[i][j]) + bias[n];
            }
        }
    }
}

// ---------------------------------------------------------------------------
// Final projection: out = g_o @ Wo^T + bo    grid (8, 128), double-buffered
// ---------------------------------------------------------------------------
__global__ void __launch_bounds__(128) mha_final_kernel(
    const float* __restrict__ W, const float* __restrict__ bias,
    float* __restrict__ C)
{
    extern __shared__ float smem[];
    float* As[2] = { smem,              smem + 2 * TILE_WORDS };
    float* Bs[2] = { smem + TILE_WORDS, smem + 3 * TILE_WORDS };

    const int tid = threadIdx.x, tx = tid & 15, ty = tid >> 4;
    const int rowBase = blockIdx.y * 64, colBase = blockIdx.x * 64;

    u64t acc[8][4];
    #pragma unroll
    for (int i = 0; i < 8; i++)
        #pragma unroll
        for (int j = 0; j < 4; j++) acc[i][j] = 0ull;

    cp_tile(As[0], g_o + (size_t)rowBase * D_MODEL, D_MODEL, tid);
    cp_tile(Bs[0], W + (size_t)colBase * D_MODEL, D_MODEL, tid);
    cp_commit();
    cp_wait0();
    __syncthreads();

    for (int c = 0; c < 8; c++) {
        int cur = c & 1;
        if (c + 1 < 8) {
            cp_tile(As[1 - cur], g_o + (size_t)rowBase * D_MODEL + (c + 1) * 64, D_MODEL, tid);
            cp_tile(Bs[1 - cur], W + (size_t)colBase * D_MODEL + (c + 1) * 64, D_MODEL, tid);
            cp_commit();
        }
        mma_tile(As[cur], Bs[cur], acc, tx, ty);
        if (c + 1 < 8) cp_wait0();
        __syncthreads();
    }

    #pragma unroll
    for (int i = 0; i < 8; i++) {
        int m = rowBase + ty * 8 + i;
        int n0 = colBase + tx * 4;
        float4 o;
        o.x = accsum(acc[i][0]) + bias[n0 + 0];
        o.y = accsum(acc[i][1]) + bias[n0 + 1];
        o.z = accsum(acc[i][2]) + bias[n0 + 2];
        o.w = accsum(acc[i][3]) + bias[n0 + 3];
        *reinterpret_cast<float4*>(C + (size_t)m * D_MODEL + n0) = o;
    }
}

// ---------------------------------------------------------------------------
// Scores: lower-triangular 64x64 tiles of q.k^T / 8. grid (NPAIRS, 16)
// (unchanged from verified R3 design — hypothesis-test kernel)
// ---------------------------------------------------------------------------
__global__ void __launch_bounds__(128) mha_scores_kernel(float* __restrict__ attn)
{
    __shared__ alignas(16) float As[64 * 64];
    __shared__ alignas(16) float Bs[64 * 64];
    int t = blockIdx.x, bh = blockIdx.y;
    int ti = (int)((sqrtf(8.0f * (float)t + 1.0f) - 1.0f) * 0.5f);
    while ((ti + 1) * (ti + 2) / 2 <= t) ti++;
    while (ti * (ti + 1) / 2 > t) ti--;
    int tj = t - ti * (ti + 1) / 2;

    int b = bh >> 3, h = bh & 7;
    const int tid = threadIdx.x, tx = tid & 15, ty = tid >> 4;

    load_tile(As, g_q + (size_t)(b * SEQ + ti * 64) * D_MODEL + h * DK, D_MODEL, tid);
    load_tile(Bs, g_k + (size_t)(b * SEQ + tj * 64) * D_MODEL + h * DK, D_MODEL, tid);
    __syncthreads();

    u64t acc[8][4];
    #pragma unroll
    for (int i = 0; i < 8; i++)
        #pragma unroll
        for (int j = 0; j < 4; j++) acc[i][j] = 0ull;

    mma_tile(As, Bs, acc, tx, ty);

    float* ob = attn + ((size_t)bh * SEQ + ti * 64) * SEQ + tj * 64;
    const float scale = 0.125f;  // 1/sqrt(64)
    #pragma unroll
    for (int i = 0; i < 8; i++) {
        int r = ty * 8 + i;
        float4 o;
        o.x = accsum(acc[i][0]) * scale;
        o.y = accsum(acc[i][1]) * scale;
        o.z = accsum(acc[i][2]) * scale;
        o.w = accsum(acc[i][3]) * scale;
        *reinterpret_cast<float4*>(ob + (size_t)r * SEQ + tx * 4) = o;
    }
}

// ---------------------------------------------------------------------------
// Row softmax (causal), float4. One block (256 thr) per row.
// Writes exact zeros for j > i (incl. never-written upper-triangular tiles).
// ---------------------------------------------------------------------------
__device__ __forceinline__ float warp_max(float v) {
    #pragma unroll
    for (int o = 16; o; o >>= 1) v = fmaxf(v, __shfl_xor_sync(0xffffffffu, v, o));
    return v;
}
__device__ __forceinline__ float warp_sum(float v) {
    #pragma unroll
    for (int o = 16; o; o >>= 1) v += __shfl_xor_sync(0xffffffffu, v, o);
    return v;
}

__global__ void mha_softmax_kernel(float* __restrict__ attn)
{
    const int row = blockIdx.x;            // bh*S + i
    const int i = row & (SEQ - 1);
    const int L = i + 1;
    float4* p4 = reinterpret_cast<float4*>(attn + (size_t)row * SEQ);
    const int tid = threadIdx.x;

    float4 x[4];
    float mx = -1e30f;
    #pragma unroll
    for (int w = 0; w < 4; w++) {
        int idx4 = tid + w * 256;
        int j0 = idx4 * 4;
        float4 v = make_float4(-1e30f, -1e30f, -1e30f, -1e30f);
        if (j0 < L) {
            v = p4[idx4];
            if (j0 + 1 >= L) v.y = -1e30f;
            if (j0 + 2 >= L) v.z = -1e30f;
            if (j0 + 3 >= L) v.w = -1e30f;
        }
        x[w] = v;
        mx = fmaxf(mx, fmaxf(fmaxf(v.x, v.y), fmaxf(v.z, v.w)));
    }

    __shared__ float red[8];
    mx = warp_max(mx);
    if ((tid & 31) == 0) red[tid >> 5] = mx;
    __syncthreads();
    float m = red[0];
    #pragma unroll
    for (int w = 1; w < 8; w++) m = fmaxf(m, red[w]);
    __syncthreads();

    float sum = 0.0f;
    #pragma unroll
    for (int w = 0; w < 4; w++) {
        x[w].x = __expf(x[w].x - m);
        x[w].y = __expf(x[w].y - m);
        x[w].z = __expf(x[w].z - m);
        x[w].w = __expf(x[w].w - m);
        sum += (x[w].x + x[w].y) + (x[w].z + x[w].w);
    }
    sum = warp_sum(sum);
    if ((tid & 31) == 0) red[tid >> 5] = sum;
    __syncthreads();
    float total = 0.0f;
    #pragma unroll
    for (int w = 0; w < 8; w++) total += red[w];
    float inv = 1.0f / total;

    #pragma unroll
    for (int w = 0; w < 4; w++) {
        float4 o = make_float4(x[w].x * inv, x[w].y * inv, x[w].z * inv, x[w].w * inv);
        p4[tid + w * 256] = o;
    }
}

// ---------------------------------------------------------------------------
// AV: o[b, i, h*64+c] = sum_{jt<=ti} attn_tile @ vt_tile.  grid (32, 16).
// Balanced pair {p, 63-p}; cp.async double-buffered over the jt loop.
// ---------------------------------------------------------------------------
__global__ void __launch_bounds__(128) mha_av_kernel(const float* __restrict__ attn)
{
    extern __shared__ float smem[];
    float* As[2] = { smem,              smem + 2 * TILE_WORDS };
    float* Bs[2] = { smem + TILE_WORDS, smem + 3 * TILE_WORDS };

    const int bh = blockIdx.y, b = bh >> 3, h = bh & 7;
    const int tid = threadIdx.x, tx = tid & 15, ty = tid >> 4;
    const float* vtb = g_vt + (size_t)(b * 512 + h * 64) * SEQ;

    #pragma unroll 1
    for (int half = 0; half < 2; half++) {
        int ti = half ? (63 - (int)blockIdx.x) : (int)blockIdx.x;
        u64t acc[8][4];
        #pragma unroll
        for (int i = 0; i < 8; i++)
            #pragma unroll
            for (int j = 0; j < 4; j++) acc[i][j] = 0ull;

        const float* ab = attn + ((size_t)bh * SEQ + ti * 64) * SEQ;
        const int nk = ti + 1;

        cp_tile(As[0], ab, SEQ, tid);
        cp_tile(Bs[0], vtb, SEQ, tid);
        cp_commit();
        cp_wait0();
        __syncthreads();

        for (int jt = 0; jt < nk; jt++) {
            int cur = jt & 1;
            if (jt + 1 < nk) {
                cp_tile(As[1 - cur], ab + (jt + 1) * 64, SEQ, tid);
                cp_tile(Bs[1 - cur], vtb + (jt + 1) * 64, SEQ, tid);
                cp_commit();
            }
            mma_tile(As[cur], Bs[cur], acc, tx, ty);
            if (jt + 1 < nk) cp_wait0();
            __syncthreads();
        }

        #pragma unroll
        for (int i = 0; i < 8; i++) {
            int m = b * SEQ + ti * 64 + ty * 8 + i;
            float4 o;
            o.x = accsum(acc[i][0]);
            o.y = accsum(acc[i][1]);
            o.z = accsum(acc[i][2]);
            o.w = accsum(acc[i][3]);
            *reinterpret_cast<float4*>(g_o + (size_t)m * D_MODEL + h * 64 + tx * 4) = o;
        }
    }
}

// ---------------------------------------------------------------------------
extern "C" void kernel_launch(void* const* d_in, const int* in_sizes, int n_in,
                              void* d_out, int out_size)
{
    const float* Q  = (const float*)d_in[0];
    const float* K  = (const float*)d_in[1];
    const float* V  = (const float*)d_in[2];
    const float* Wq = (const float*)d_in[3];
    const float* bq = (const float*)d_in[4];
    const float* Wk = (const float*)d_in[5];
    const float* bk = (const float*)d_in[6];
    const float* Wv = (const float*)d_in[7];
    const float* bv = (const float*)d_in[8];
    const float* Wo = (const float*)d_in[9];
    const float* bo = (const float*)d_in[10];

    float* outp = (float*)d_out;
    long long oe = (long long)out_size;

    float* final_out = nullptr;   // where `out` [B,S,D] goes (nullptr = skip)
    float* attn      = nullptr;   // where `attn` [B,H,S,S] goes
    if (oe >= (long long)OUT_ELEMS + ATTN_ELEMS) {
        final_out = outp;
        attn      = outp + OUT_ELEMS;
    } else if (oe >= ATTN_ELEMS) {
        attn = outp;               // attn-only output
    } else {
        final_out = outp;          // out-only; attn in device scratch
        void* sp = nullptr;
        cudaGetSymbolAddress(&sp, g_attn_scratch);  // address lookup only; capture-safe
        attn = (float*)sp;
    }

    const int DBUF_SMEM = 4 * TILE_WORDS * (int)sizeof(float);  // 64 KB
    // Unconditional (no static guards — harness rule). Idempotent; capture-safe.
    cudaFuncSetAttribute(mha_qkv_kernel,
                         cudaFuncAttributeMaxDynamicSharedMemorySize, DBUF_SMEM);
    cudaFuncSetAttribute(mha_final_kernel,
                         cudaFuncAttributeMaxDynamicSharedMemorySize, DBUF_SMEM);
    cudaFuncSetAttribute(mha_av_kernel,
                         cudaFuncAttributeMaxDynamicSharedMemorySize, DBUF_SMEM);

    dim3 gqkv(8, 128, 3);

    mha_qkv_kernel<<<gqkv, 128, DBUF_SMEM>>>(Q, K, V, Wq, bq, Wk, bk, Wv, bv);
    mha_scores_kernel<<<dim3(NPAIRS, 16), 128>>>(attn);
    mha_softmax_kernel<<<BATCH * NHEADS * SEQ, 256>>>(attn);
    if (final_out) {
        mha_av_kernel<<<dim3(32, 16), 128, DBUF_SMEM>>>(attn);
        mha_final_kernel<<<dim3(8, 128), 128, DBUF_SMEM>>>(Wo, bo, final_out);
    }
}